// round 15
// baseline (speedup 1.0000x reference)
#include <cuda_runtime.h>
#include <math.h>

#define NMAX 50000
#define EMAX 800000
#define ETMAX (NMAX + EMAX)
#define BMAX 512
#define SCAN_BLK 256
#define GROWS 12

// ---------------- scratch (device globals; no allocations allowed) ----------
__device__ float g_xl[NMAX * 128];
__device__ float g_xr[NMAX * 128];
__device__ float g_h[NMAX * 128];
__device__ int   g_src[ETMAX];
__device__ int   g_dst[ETMAX];
__device__ int   g_csrc[ETMAX];      // src node per dst-sorted edge
__device__ int   g_deg[NMAX];
__device__ int   g_scan[NMAX];
__device__ int   g_bsum[SCAN_BLK];
__device__ int   g_rowptr[NMAX + 1];
__device__ int   g_cursor[NMAX];
__device__ int   g_batch[NMAX];
__device__ float g_pool[BMAX * 32];
__device__ float g_cnt[BMAX];
__device__ int   g_is64;
// packed weights: wp[kk][col] = ulonglong2{(W[4kk],W[4kk+1]),(W[4kk+2],W[4kk+3])}
__device__ ulonglong2 g_wpl[32 * 128];
__device__ ulonglong2 g_wpr[32 * 128];

// ---------------- f32x2 packed math helpers ---------------------------------
__device__ __forceinline__ unsigned long long pack2(float lo, float hi) {
    unsigned long long r;
    asm("mov.b64 %0, {%1, %2};" : "=l"(r) : "f"(lo), "f"(hi));
    return r;
}
__device__ __forceinline__ void fma2(unsigned long long& acc,
                                     unsigned long long a,
                                     unsigned long long b) {
    asm("fma.rn.f32x2 %0, %1, %2, %0;" : "+l"(acc) : "l"(a), "l"(b));
}
__device__ __forceinline__ float hsum2(unsigned long long v) {
    float lo, hi;
    asm("mov.b64 {%0, %1}, %2;" : "=f"(lo), "=f"(hi) : "l"(v));
    return lo + hi;
}

// ---------------- dtype sniff: int64 vs int32 edge_index --------------------
__global__ void detect_kernel(const void* ei) {
    __shared__ int s;
    if (threadIdx.x == 0) s = 0;
    __syncthreads();
    const int* w = (const int*)ei;
    int v = w[2 * threadIdx.x + 1];
    atomicOr(&s, v);
    __syncthreads();
    if (threadIdx.x == 0) g_is64 = (s == 0) ? 1 : 0;
}

// Zero degree counters (must run before convert's fused histogram).
__global__ void zero_deg_kernel(int N) {
    int i = blockIdx.x * blockDim.x + threadIdx.x;
    if (i < N) g_deg[i] = 0;
}

// Convert edge_index (+ self loops) and batch to int32; fused degree histogram.
__global__ void convert_kernel(const void* ei, const void* batch, int E, int N) {
    int i = blockIdx.x * blockDim.x + threadIdx.x;
    int is64 = g_is64;
    if (i < E) {
        int s, d;
        if (is64) {
            const long long* p = (const long long*)ei;
            s = (int)p[i]; d = (int)p[(long long)E + i];
        } else {
            const int* p = (const int*)ei;
            s = p[i]; d = p[E + i];
        }
        g_src[i] = s; g_dst[i] = d;
        atomicAdd(&g_deg[d], 1);
    } else if (i < E + N) {
        int n = i - E;
        g_src[i] = n; g_dst[i] = n;
        atomicAdd(&g_deg[n], 1);
    }
    if (i < N) {
        g_batch[i] = is64 ? (int)((const long long*)batch)[i]
                          : ((const int*)batch)[i];
    }
}

// ---------------- weight pre-pack -------------------------------------------
__global__ void pack_w_kernel(const float* __restrict__ Wl,
                              const float* __restrict__ Wr, int DOUT) {
    int i = blockIdx.x * blockDim.x + threadIdx.x;
    int tot = 32 * DOUT;
    if (i >= 2 * tot) return;
    const float* W = (i < tot) ? Wl : Wr;
    int j = (i < tot) ? i : i - tot;
    int kk = j / DOUT, col = j - kk * DOUT;
    ulonglong2 v;
    v.x = pack2(W[(4 * kk + 0) * DOUT + col], W[(4 * kk + 1) * DOUT + col]);
    v.y = pack2(W[(4 * kk + 2) * DOUT + col], W[(4 * kk + 3) * DOUT + col]);
    if (i < tot) g_wpl[j] = v; else g_wpr[j] = v;
}

// ---------------- CSR build: scan -> scatter --------------------------------
__global__ void scan1_kernel(int N) {
    __shared__ int sh[SCAN_BLK];
    int i = blockIdx.x * SCAN_BLK + threadIdx.x;
    int v = (i < N) ? g_deg[i] : 0;
    sh[threadIdx.x] = v;
    __syncthreads();
    for (int off = 1; off < SCAN_BLK; off <<= 1) {
        int t = (threadIdx.x >= off) ? sh[threadIdx.x - off] : 0;
        __syncthreads();
        sh[threadIdx.x] += t;
        __syncthreads();
    }
    if (i < N) g_scan[i] = sh[threadIdx.x];
    if (threadIdx.x == SCAN_BLK - 1) g_bsum[blockIdx.x] = sh[threadIdx.x];
}

__global__ void scan2_kernel(int nb) {
    __shared__ int sh[SCAN_BLK];
    int t = threadIdx.x;
    int v = (t < nb) ? g_bsum[t] : 0;
    sh[t] = v;
    __syncthreads();
    for (int off = 1; off < SCAN_BLK; off <<= 1) {
        int u = (t >= off) ? sh[t - off] : 0;
        __syncthreads();
        sh[t] += u;
        __syncthreads();
    }
    g_bsum[t] = sh[t] - v;  // exclusive
}

__global__ void scan3_kernel(int N) {
    int i = blockIdx.x * blockDim.x + threadIdx.x;
    if (i >= N) return;
    int incl = g_scan[i] + g_bsum[i >> 8];
    g_rowptr[i + 1] = incl;
    g_cursor[i] = incl - g_deg[i];
    if (i == 0) g_rowptr[0] = 0;
}

__global__ void scatter_kernel(int ET) {
    int i = blockIdx.x * blockDim.x + threadIdx.x;
    if (i >= ET) return;
    int d = g_dst[i];
    int pos = atomicAdd(&g_cursor[d], 1);
    g_csrc[pos] = g_src[i];
}

// ---------------- dual GEMM: Yl/Yr[N,128] = X[N,128] @ {Wl,Wr} + b ----------
// 64 threads, each owning columns {tid, tid+64} of BOTH matrices; GROWS=12
// rows per block. Rows/block is the L2 lever: each block reads the full 128KB
// packed-weight set from L2, so traffic = (N/GROWS)*128KB. 12 rows puts the
// L2 bound (~53us) at the FFMA2 floor (~48us) without register spill.
__global__ void __launch_bounds__(64) gemm128_dual_kernel(
        const float* __restrict__ X,
        const float* __restrict__ bl,
        const float* __restrict__ br,
        float* __restrict__ Yl,
        float* __restrict__ Yr, int N) {
    __shared__ float4 sh[GROWS * 32];
    int n0 = blockIdx.x * GROWS;
    int tid = threadIdx.x;
    int c0 = tid, c1 = tid + 64;
    const float4* Xv = (const float4*)X;
    for (int i = tid; i < GROWS * 32; i += 64) {
        int r = i >> 5, c = i & 31;
        int n = n0 + r;
        sh[i] = (n < N) ? Xv[(size_t)n * 32 + c] : make_float4(0.f, 0.f, 0.f, 0.f);
    }
    __syncthreads();
    unsigned long long al0[GROWS], al1[GROWS], ar0[GROWS], ar1[GROWS];
#pragma unroll
    for (int r = 0; r < GROWS; r++) { al0[r] = al1[r] = ar0[r] = ar1[r] = 0ull; }
    const ulonglong2* shv = (const ulonglong2*)sh;
#pragma unroll 4
    for (int kk = 0; kk < 32; kk++) {
        ulonglong2 wl0 = g_wpl[kk * 128 + c0];
        ulonglong2 wl1 = g_wpl[kk * 128 + c1];
        ulonglong2 wr0 = g_wpr[kk * 128 + c0];
        ulonglong2 wr1 = g_wpr[kk * 128 + c1];
#pragma unroll
        for (int r = 0; r < GROWS; r++) {
            ulonglong2 xv = shv[r * 32 + kk];
            fma2(al0[r], xv.x, wl0.x); fma2(al0[r], xv.y, wl0.y);
            fma2(al1[r], xv.x, wl1.x); fma2(al1[r], xv.y, wl1.y);
            fma2(ar0[r], xv.x, wr0.x); fma2(ar0[r], xv.y, wr0.y);
            fma2(ar1[r], xv.x, wr1.x); fma2(ar1[r], xv.y, wr1.y);
        }
    }
    float bl0 = bl[c0], bl1 = bl[c1], br0 = br[c0], br1 = br[c1];
#pragma unroll
    for (int r = 0; r < GROWS; r++) {
        int n = n0 + r;
        if (n < N) {
            Yl[(size_t)n * 128 + c0] = hsum2(al0[r]) + bl0;
            Yl[(size_t)n * 128 + c1] = hsum2(al1[r]) + bl1;
            Yr[(size_t)n * 128 + c0] = hsum2(ar0[r]) + br0;
            Yr[(size_t)n * 128 + c1] = hsum2(ar1[r]) + br1;
        }
    }
}

// dual GEMM DOUT=32: lane = column, 4 warps x 16 rows = 64 rows per block.
__global__ void gemm32_dual_kernel(const float* __restrict__ X,
                                   const float* __restrict__ bl,
                                   const float* __restrict__ br,
                                   float* __restrict__ Yl,
                                   float* __restrict__ Yr, int N) {
    __shared__ float4 sh[64 * 32];
    int n0 = blockIdx.x * 64;
    int tid = threadIdx.x;
    int warp = tid >> 5, lane = tid & 31;
    const float4* Xv = (const float4*)X;
    for (int i = tid; i < 64 * 32; i += 128) {
        int r = i >> 5, c = i & 31;
        int n = n0 + r;
        sh[i] = (n < N) ? Xv[(size_t)n * 32 + c] : make_float4(0.f, 0.f, 0.f, 0.f);
    }
    __syncthreads();
    unsigned long long accl[16], accr[16];
#pragma unroll
    for (int r = 0; r < 16; r++) { accl[r] = 0ull; accr[r] = 0ull; }
    const ulonglong2* shv = (const ulonglong2*)sh;
#pragma unroll 4
    for (int kk = 0; kk < 32; kk++) {
        ulonglong2 wl = g_wpl[kk * 32 + lane];
        ulonglong2 wr = g_wpr[kk * 32 + lane];
#pragma unroll
        for (int r = 0; r < 16; r++) {
            ulonglong2 xv = shv[(warp * 16 + r) * 32 + kk];
            fma2(accl[r], xv.x, wl.x);
            fma2(accl[r], xv.y, wl.y);
            fma2(accr[r], xv.x, wr.x);
            fma2(accr[r], xv.y, wr.y);
        }
    }
    float bbl = bl[lane], bbr = br[lane];
#pragma unroll
    for (int r = 0; r < 16; r++) {
        int n = n0 + warp * 16 + r;
        if (n < N) {
            Yl[(size_t)n * 32 + lane] = hsum2(accl[r]) + bbl;
            Yr[(size_t)n * 32 + lane] = hsum2(accr[r]) + bbr;
        }
    }
}

// ---------------- node-kernel helpers ----------------------------------------
__device__ __forceinline__ float edot4(float4 a, float4 xr, float4 at) {
    float t0 = a.x + xr.x; t0 = t0 > 0.f ? t0 : 0.2f * t0;
    float t1 = a.y + xr.y; t1 = t1 > 0.f ? t1 : 0.2f * t1;
    float t2 = a.z + xr.z; t2 = t2 > 0.f ? t2 : 0.2f * t2;
    float t3 = a.w + xr.w; t3 = t3 > 0.f ? t3 : 0.2f * t3;
    return t0 * at.x + t1 * at.y + t2 * at.z + t3 * at.w;
}
__device__ __forceinline__ void osm_update(float& m, float& d, float4& acc,
                                           float p, float4 a) {
    if (p > m) {
        float sc = __expf(m - p);  // exp(-inf)=0 on first edge
        d *= sc;
        acc.x *= sc; acc.y *= sc; acc.z *= sc; acc.w *= sc;
        m = p;
    }
    float w = __expf(p - m);
    d += w;
    acc.x += w * a.x; acc.y += w * a.y; acc.z += w * a.z; acc.w += w * a.w;
}

// ---------------- fused GATv2 per-node kernel, H=4 ---------------------------
// Warp per dst node. Lane owns channels [4*lane, 4*lane+4) = head lane/8.
// 4 edges in flight per iteration: 4 LDG.128 up front, 4 interleaved shfl
// chains, then 4 online-softmax updates. Zero atomics.
__global__ void gat_node4_kernel(const float* __restrict__ att,
                                 const float* __restrict__ bias, int N) {
    int n = (blockIdx.x * blockDim.x + threadIdx.x) >> 5;
    int lane = threadIdx.x & 31;
    if (n >= N) return;

    float4 attv = __ldg((const float4*)att + lane);
    float4 xrv = *(const float4*)(g_xr + (size_t)n * 128 + 4 * lane);
    float m = -INFINITY, d = 0.f;
    float4 acc = make_float4(0.f, 0.f, 0.f, 0.f);

    int e = g_rowptr[n], end = g_rowptr[n + 1];
    for (; e + 3 < end; e += 4) {
        int s0 = g_csrc[e], s1 = g_csrc[e + 1];
        int s2 = g_csrc[e + 2], s3 = g_csrc[e + 3];
        float4 a0 = *(const float4*)(g_xl + (size_t)s0 * 128 + 4 * lane);
        float4 a1 = *(const float4*)(g_xl + (size_t)s1 * 128 + 4 * lane);
        float4 a2 = *(const float4*)(g_xl + (size_t)s2 * 128 + 4 * lane);
        float4 a3 = *(const float4*)(g_xl + (size_t)s3 * 128 + 4 * lane);
        float p0 = edot4(a0, xrv, attv);
        float p1 = edot4(a1, xrv, attv);
        float p2 = edot4(a2, xrv, attv);
        float p3 = edot4(a3, xrv, attv);
        p0 += __shfl_xor_sync(0xffffffffu, p0, 1);
        p1 += __shfl_xor_sync(0xffffffffu, p1, 1);
        p2 += __shfl_xor_sync(0xffffffffu, p2, 1);
        p3 += __shfl_xor_sync(0xffffffffu, p3, 1);
        p0 += __shfl_xor_sync(0xffffffffu, p0, 2);
        p1 += __shfl_xor_sync(0xffffffffu, p1, 2);
        p2 += __shfl_xor_sync(0xffffffffu, p2, 2);
        p3 += __shfl_xor_sync(0xffffffffu, p3, 2);
        p0 += __shfl_xor_sync(0xffffffffu, p0, 4);
        p1 += __shfl_xor_sync(0xffffffffu, p1, 4);
        p2 += __shfl_xor_sync(0xffffffffu, p2, 4);
        p3 += __shfl_xor_sync(0xffffffffu, p3, 4);
        osm_update(m, d, acc, p0, a0);
        osm_update(m, d, acc, p1, a1);
        osm_update(m, d, acc, p2, a2);
        osm_update(m, d, acc, p3, a3);
    }
    for (; e < end; e++) {
        int s0 = g_csrc[e];
        float4 a0 = *(const float4*)(g_xl + (size_t)s0 * 128 + 4 * lane);
        float p0 = edot4(a0, xrv, attv);
        p0 += __shfl_xor_sync(0xffffffffu, p0, 1);
        p0 += __shfl_xor_sync(0xffffffffu, p0, 2);
        p0 += __shfl_xor_sync(0xffffffffu, p0, 4);
        osm_update(m, d, acc, p0, a0);
    }

    float inv = 1.f / (d + 1e-16f);
    float4 bi = __ldg((const float4*)bias + lane);
    float4 v;
    v.x = acc.x * inv + bi.x; v.x = v.x > 0.f ? v.x : (__expf(v.x) - 1.f);
    v.y = acc.y * inv + bi.y; v.y = v.y > 0.f ? v.y : (__expf(v.y) - 1.f);
    v.z = acc.z * inv + bi.z; v.z = v.z > 0.f ? v.z : (__expf(v.z) - 1.f);
    v.w = acc.w * inv + bi.w; v.w = v.w > 0.f ? v.w : (__expf(v.w) - 1.f);
    *(float4*)(g_h + (size_t)n * 128 + 4 * lane) = v;
}

// ---------------- fused GATv2 per-node kernel, H=1 + pooling -----------------
__global__ void gat_node1_kernel(const float* __restrict__ att,
                                 const float* __restrict__ bias, int N) {
    int n = (blockIdx.x * blockDim.x + threadIdx.x) >> 5;
    int lane = threadIdx.x & 31;
    if (n >= N) return;
    int grp = lane >> 3, sl = lane & 7;

    float4 attv = __ldg((const float4*)att + sl);
    float4 xrv = *(const float4*)(g_xr + (size_t)n * 32 + 4 * sl);
    float m = -INFINITY, d = 0.f;
    float4 acc = make_float4(0.f, 0.f, 0.f, 0.f);

    int start = g_rowptr[n], end = g_rowptr[n + 1];
    for (int eb = start; eb < end; eb += 4) {
        int me = eb + grp;
        bool valid = me < end;
        int s = valid ? g_csrc[me] : g_csrc[eb];
        float4 a = *(const float4*)(g_xl + (size_t)s * 32 + 4 * sl);
        float p = edot4(a, xrv, attv);
        p += __shfl_xor_sync(0xffffffffu, p, 1);
        p += __shfl_xor_sync(0xffffffffu, p, 2);
        p += __shfl_xor_sync(0xffffffffu, p, 4);
        if (valid) osm_update(m, d, acc, p, a);
    }

    // merge the 4 group states (xor 8, then 16)
#pragma unroll
    for (int off = 8; off <= 16; off <<= 1) {
        float mo = __shfl_xor_sync(0xffffffffu, m, off);
        float do_ = __shfl_xor_sync(0xffffffffu, d, off);
        float4 ao;
        ao.x = __shfl_xor_sync(0xffffffffu, acc.x, off);
        ao.y = __shfl_xor_sync(0xffffffffu, acc.y, off);
        ao.z = __shfl_xor_sync(0xffffffffu, acc.z, off);
        ao.w = __shfl_xor_sync(0xffffffffu, acc.w, off);
        float nm = fmaxf(m, mo);
        float s1 = (m == nm) ? 1.f : __expf(m - nm);
        float s2 = (mo == nm) ? 1.f : __expf(mo - nm);
        d = d * s1 + do_ * s2;
        acc.x = acc.x * s1 + ao.x * s2;
        acc.y = acc.y * s1 + ao.y * s2;
        acc.z = acc.z * s1 + ao.z * s2;
        acc.w = acc.w * s1 + ao.w * s2;
        m = nm;
    }

    if (grp == 0) {
        float inv = 1.f / (d + 1e-16f);
        float4 bi = __ldg((const float4*)bias + sl);
        float4 v;
        v.x = acc.x * inv + bi.x; v.x = v.x > 0.f ? v.x : (__expf(v.x) - 1.f);
        v.y = acc.y * inv + bi.y; v.y = v.y > 0.f ? v.y : (__expf(v.y) - 1.f);
        v.z = acc.z * inv + bi.z; v.z = v.z > 0.f ? v.z : (__expf(v.z) - 1.f);
        v.w = acc.w * inv + bi.w; v.w = v.w > 0.f ? v.w : (__expf(v.w) - 1.f);
        int b = g_batch[n];
        atomicAdd(&g_pool[b * 32 + 4 * sl + 0], v.x);
        atomicAdd(&g_pool[b * 32 + 4 * sl + 1], v.y);
        atomicAdd(&g_pool[b * 32 + 4 * sl + 2], v.z);
        atomicAdd(&g_pool[b * 32 + 4 * sl + 3], v.w);
        if (sl == 0) atomicAdd(&g_cnt[b], 1.f);
    }
}

// ---------------- pooling init + MLP head -----------------------------------
__global__ void pool_init_kernel(int B) {
    int i = blockIdx.x * blockDim.x + threadIdx.x;
    if (i < B * 32) g_pool[i] = 0.f;
    if (i < B) g_cnt[i] = 0.f;
}

__global__ void head_kernel(const float* __restrict__ meta,
                            const float* __restrict__ Wh1,
                            const float* __restrict__ bh1,
                            const float* __restrict__ Wh2,
                            const float* __restrict__ bh2,
                            float* __restrict__ out, int B) {
    int g = (blockIdx.x * blockDim.x + threadIdx.x) >> 5;
    int lane = threadIdx.x & 31;
    if (g >= B) return;
    float c = g_cnt[g];
    if (c < 1.f) c = 1.f;
    float inv = 1.f / c;
    float acc = bh1[lane];
    for (int k = 0; k < 32; k++)
        acc += g_pool[g * 32 + k] * inv * Wh1[k * 32 + lane];
    for (int k = 0; k < 12; k++)
        acc += meta[g * 12 + k] * Wh1[(32 + k) * 32 + lane];
    acc = acc > 0.f ? acc : 0.f;
    float r = acc * Wh2[lane];
#pragma unroll
    for (int off = 16; off; off >>= 1)
        r += __shfl_xor_sync(0xffffffffu, r, off);
    if (lane == 0) out[g] = r + bh2[0];
}

// ---------------- host ------------------------------------------------------
extern "C" void kernel_launch(void* const* d_in, const int* in_sizes, int n_in,
                              void* d_out, int out_size) {
    const float* x     = (const float*)d_in[0];
    const void*  ei    = d_in[1];
    const void*  batch = d_in[2];
    const float* meta  = (const float*)d_in[3];

    const float *Wl[3], *bl[3], *Wr[3], *br[3], *att[3], *bo[3];
    for (int l = 0; l < 3; l++) {
        int base = 4 + 6 * l;
        Wl[l]  = (const float*)d_in[base + 0];
        bl[l]  = (const float*)d_in[base + 1];
        Wr[l]  = (const float*)d_in[base + 2];
        br[l]  = (const float*)d_in[base + 3];
        att[l] = (const float*)d_in[base + 4];
        bo[l]  = (const float*)d_in[base + 5];
    }
    const float* Wh1 = (const float*)d_in[22];
    const float* bh1 = (const float*)d_in[23];
    const float* Wh2 = (const float*)d_in[24];
    const float* bh2 = (const float*)d_in[25];

    int N = in_sizes[0] / 128;
    int E = in_sizes[1] / 2;
    int ET = E + N;
    int B = in_sizes[3] / 12;
    float* out = (float*)d_out;

    float *p_xl, *p_xr, *p_h;
    cudaGetSymbolAddress((void**)&p_xl, g_xl);
    cudaGetSymbolAddress((void**)&p_xr, g_xr);
    cudaGetSymbolAddress((void**)&p_h, g_h);

    int ggemm = (N + GROWS - 1) / GROWS;
    int g64 = (N + 63) / 64;
    int node_blocks = (N * 32 + 255) / 256;
    int pack128_blocks = (2 * 32 * 128 + 255) / 256;
    int pack32_blocks = (2 * 32 * 32 + 255) / 256;

    // ---- prolog; gemm128_dual is launch #4 (the ncu capture slot)
    detect_kernel<<<1, 256>>>(ei);
    pack_w_kernel<<<pack128_blocks, 256>>>(Wl[0], Wr[0], 128);
    zero_deg_kernel<<<(N + 255) / 256, 256>>>(N);
    gemm128_dual_kernel<<<ggemm, 64>>>(x, bl[0], br[0], p_xl, p_xr, N);
    convert_kernel<<<(ET + 255) / 256, 256>>>(ei, batch, E, N);

    // ---- CSR build (once; graph shared by all layers)
    int nb = (N + SCAN_BLK - 1) / SCAN_BLK;
    scan1_kernel<<<nb, SCAN_BLK>>>(N);
    scan2_kernel<<<1, SCAN_BLK>>>(nb);
    scan3_kernel<<<(N + 255) / 256, 256>>>(N);
    scatter_kernel<<<(ET + 255) / 256, 256>>>(ET);
    pool_init_kernel<<<(B * 32 + 255) / 256, 256>>>(B);

    // ---- layer 0 attention
    gat_node4_kernel<<<node_blocks, 256>>>(att[0], bo[0], N);

    // ---- layer 1
    pack_w_kernel<<<pack128_blocks, 256>>>(Wl[1], Wr[1], 128);
    gemm128_dual_kernel<<<ggemm, 64>>>(p_h, bl[1], br[1], p_xl, p_xr, N);
    gat_node4_kernel<<<node_blocks, 256>>>(att[1], bo[1], N);

    // ---- layer 2: H=1, DOUT=32, pool fused into epilogue
    pack_w_kernel<<<pack32_blocks, 256>>>(Wl[2], Wr[2], 32);
    gemm32_dual_kernel<<<g64, 128>>>(p_h, bl[2], br[2], p_xl, p_xr, N);
    gat_node1_kernel<<<node_blocks, 256>>>(att[2], bo[2], N);

    // ---- MLP head
    head_kernel<<<(B * 32 + 255) / 256, 256>>>(meta, Wh1, bh1, Wh2, bh2, out, B);
}